// round 3
// baseline (speedup 1.0000x reference)
#include <cuda_runtime.h>
#include <cuda_bf16.h>

#define ROW_N 4096
#define THREADS 512
#define REPS 8           // outputs per thread per stage (512*8 = 4096)

// One CTA per 4096-point row. Monarch decomposition (P = Q = 64):
//   A[p,q]       = x[p + 64 q]
//   B[p,k]       = sum_q A[p,q] * exp(-2pi i q k / 64)
//   C[p,k]       = B[p,k] * exp(-2pi i p k / 4096)
//   out[j*64+k]  = sum_p exp(-2pi i j p / 64) * C[p,k]
//
// Output handling (deduced from harness faults): out_size == N  ->  the
// harness buffer holds N float32 = Re(D) (complex64 coerced to float32).
// mode 0: store real part only.  mode 1 (out_size >= 2N): interleaved
// complex float2. All global stores are guarded by out_limit (in floats).
__global__ void __launch_bounds__(THREADS, 2)
monarch_fft_kernel(const float* __restrict__ x, float* __restrict__ out,
                   int mode, long long out_limit)
{
    __shared__ float2 Cs[64 * 65];   // pitch 65 -> stage-2 reads conflict-free
    __shared__ float2 T64[64];       // exp(-2pi i t / 64)
    __shared__ float2 Tf [64];       // exp(-2pi i t / 4096)

    float* xs = (float*)Cs;          // 4096 floats, overlays Cs (dead after S1)

    const int row = blockIdx.x;
    const int tid = threadIdx.x;

    if (tid < 64) {
        float s, c;
        __sincosf(-6.28318530717958647692f * (float)tid * (1.0f / 64.0f), &s, &c);
        T64[tid] = make_float2(c, s);
        __sincosf(-6.28318530717958647692f * (float)tid * (1.0f / 4096.0f), &s, &c);
        Tf[tid] = make_float2(c, s);
    }

    const float* __restrict__ xr = x + (size_t)row * ROW_N;
    #pragma unroll
    for (int i = tid; i < ROW_N; i += THREADS) xs[i] = xr[i];
    __syncthreads();

    // ---- Stage 1: B[p, k_r],  p = tid&63 (lane-varying), k_r = (tid>>6)+8r ----
    const int p  = tid & 63;
    const int kb = tid >> 6;
    float br[REPS], bi[REPS];
    int   t [REPS];
    #pragma unroll
    for (int r = 0; r < REPS; r++) { br[r] = 0.f; bi[r] = 0.f; t[r] = 0; }

    #pragma unroll 4
    for (int q = 0; q < 64; q++) {
        const float a = xs[p + (q << 6)];          // conflict-free, reused 8x
        #pragma unroll
        for (int r = 0; r < REPS; r++) {
            const float2 w = T64[t[r]];            // warp-uniform -> broadcast
            br[r] = fmaf(a, w.x, br[r]);
            bi[r] = fmaf(a, w.y, bi[r]);
            t[r] = (t[r] + kb + 8 * r) & 63;       // t = q * k_r mod 64
        }
    }
    __syncthreads();                               // xs dead -> Cs may overwrite

    #pragma unroll
    for (int r = 0; r < REPS; r++) {
        const int k  = kb + 8 * r;
        const int tt = p * k;                      // < 4096
        const float2 w1 = T64[tt >> 6];
        const float2 w2 = Tf [tt & 63];
        const float wr = w1.x * w2.x - w1.y * w2.y;
        const float wi = w1.x * w2.y + w1.y * w2.x;
        Cs[p * 65 + k] = make_float2(br[r] * wr - bi[r] * wi,
                                     br[r] * wi + bi[r] * wr);
    }
    __syncthreads();

    // ---- Stage 2: D[j_r, k],  k = tid&63 (lane-varying), j_r = (tid>>6)+8r ----
    const int k  = tid & 63;
    const int jb = tid >> 6;
    float dr[REPS], di[REPS];
    int   u [REPS];
    #pragma unroll
    for (int r = 0; r < REPS; r++) { dr[r] = 0.f; di[r] = 0.f; u[r] = 0; }

    #pragma unroll 2
    for (int pp = 0; pp < 64; pp++) {
        const float2 c = Cs[pp * 65 + k];          // conflict-free, reused 8x
        #pragma unroll
        for (int r = 0; r < REPS; r++) {
            const float2 w = T64[u[r]];            // broadcast
            dr[r] = fmaf(c.x, w.x, fmaf(-c.y, w.y, dr[r]));
            di[r] = fmaf(c.x, w.y, fmaf( c.y, w.x, di[r]));
            u[r] = (u[r] + jb + 8 * r) & 63;       // u = pp * j_r mod 64
        }
    }

    if (mode == 0) {
        // Real part only: out is float[nrows*4096]
        #pragma unroll
        for (int r = 0; r < REPS; r++) {
            const long long gidx = (long long)row * ROW_N + (jb + 8 * r) * 64 + k;
            if (gidx < out_limit) out[gidx] = dr[r];          // coalesced 4B
        }
    } else {
        // Interleaved complex: out is float2[nrows*4096]
        float2* __restrict__ outc = (float2*)out;
        #pragma unroll
        for (int r = 0; r < REPS; r++) {
            const long long gidx = (long long)row * ROW_N + (jb + 8 * r) * 64 + k;
            if (2 * gidx + 1 < out_limit)
                outc[gidx] = make_float2(dr[r], di[r]);        // coalesced 8B
        }
    }
}

extern "C" void kernel_launch(void* const* d_in, const int* in_sizes, int n_in,
                              void* d_out, int out_size)
{
    const float* x = (const float*)d_in[0];
    const long long total = (long long)in_sizes[0];    // 16,777,216
    const int nrows = (int)(total / ROW_N);            // 4096 rows
    if (nrows <= 0) return;

    // out_size >= 2*total  -> buffer holds interleaved complex (float pairs)
    // otherwise            -> buffer holds out_size float32 = real part
    const int mode = ((long long)out_size >= 2 * total) ? 1 : 0;

    monarch_fft_kernel<<<nrows, THREADS>>>(x, (float*)d_out, mode,
                                           (long long)out_size);
}

// round 4
// speedup vs baseline: 2.0466x; 2.0466x over previous
#include <cuda_runtime.h>
#include <cuda_bf16.h>

#define ROW_N 4096
#define THREADS 512

// One CTA per 4096-point row of a real-input FFT; output = Re(FFT(x)).
// Monarch decomposition (P = Q = 64):
//   B[p,k]      = sum_q x[p+64q] * exp(-2pi i q k/64)      (real input!)
//   C[p,k]      = B[p,k] * exp(-2pi i p k/4096)
//   D[j*64+k]   = sum_p exp(-2pi i j p/64) * C[p,k],   out = Re(D)
//
// Symmetries used:
//   B[p,64-k] = conj(B[p,k])      -> stage 1 computes k = 0..31 (+k=32 special)
//   Re(D[m])  = Re(D[4096-m])     -> stage 2 computes j = 0..31 (+j=32 special),
//                                    mirror-stores m' = 4096-m (disjoint sets).
__global__ void __launch_bounds__(THREADS, 2)
monarch_fft_kernel(const float* __restrict__ x, float* __restrict__ out)
{
    __shared__ float2 Cs[64 * 65];   // pitch 65 -> conflict-free stage-2 reads
    __shared__ float2 T64[64];       // exp(-2pi i t / 64)
    __shared__ float2 Tf [64];       // exp(-2pi i t / 4096)

    float* xs = (float*)Cs;          // 4096 floats; dead before Cs is written

    const int row = blockIdx.x;
    const int tid = threadIdx.x;

    if (tid < 64) {
        float s, c;
        __sincosf(-6.28318530717958647692f * (float)tid * (1.0f / 64.0f), &s, &c);
        T64[tid] = make_float2(c, s);
        __sincosf(-6.28318530717958647692f * (float)tid * (1.0f / 4096.0f), &s, &c);
        Tf[tid] = make_float2(c, s);
    }

    const float* __restrict__ xr = x + (size_t)row * ROW_N;
    #pragma unroll
    for (int i = tid; i < ROW_N; i += THREADS) xs[i] = xr[i];
    __syncthreads();

    // ---- Stage 1: B[p,k] for p in {p0, p0+32}, k in {k0, k0+16} ----
    // p0 = lane (0..31) -> xs reads conflict-free; k0 warp-uniform -> T64 broadcast.
    const int p0 = tid & 31;
    const int k0 = tid >> 5;         // 0..15
    float br[2][2] = {{0.f,0.f},{0.f,0.f}};
    float bi[2][2] = {{0.f,0.f},{0.f,0.f}};
    int   t[2]     = {0, 0};

    #pragma unroll 4
    for (int q = 0; q < 64; q++) {
        const float a0 = xs[p0      + (q << 6)];
        const float a1 = xs[p0 + 32 + (q << 6)];
        #pragma unroll
        for (int ki = 0; ki < 2; ki++) {
            const float2 w = T64[t[ki]];          // broadcast
            br[0][ki] = fmaf(a0, w.x, br[0][ki]);
            bi[0][ki] = fmaf(a0, w.y, bi[0][ki]);
            br[1][ki] = fmaf(a1, w.x, br[1][ki]);
            bi[1][ki] = fmaf(a1, w.y, bi[1][ki]);
            t[ki] = (t[ki] + k0 + 16 * ki) & 63;  // t = q*k mod 64
        }
    }

    // k = 32 column: B[p,32] = sum_q (-1)^q xs[p+64q]  (real)
    float b32 = 0.f;
    if (tid < 64) {
        #pragma unroll 8
        for (int q = 0; q < 64; q += 2)
            b32 += xs[tid + (q << 6)] - xs[tid + ((q + 1) << 6)];
    }
    __syncthreads();                 // all xs reads done -> Cs may overwrite

    // ---- Twiddle + write C (direct k and Hermitian mirror 64-k) ----
    #pragma unroll
    for (int pi = 0; pi < 2; pi++) {
        const int p = p0 + 32 * pi;
        #pragma unroll
        for (int ki = 0; ki < 2; ki++) {
            const int k = k0 + 16 * ki;           // 0..31
            const float R = br[pi][ki], I = bi[pi][ki];
            {
                const int tt = p * k;             // < 4096
                const float2 w1 = T64[tt >> 6], w2 = Tf[tt & 63];
                const float wr = w1.x * w2.x - w1.y * w2.y;
                const float wi = w1.x * w2.y + w1.y * w2.x;
                Cs[p * 65 + k] = make_float2(R * wr - I * wi, R * wi + I * wr);
            }
            if (k > 0) {                          // mirror: C[p,64-k] = conj(B)*tw
                const int km = 64 - k;
                const int tt = p * km;            // < 4096
                const float2 w1 = T64[tt >> 6], w2 = Tf[tt & 63];
                const float wr = w1.x * w2.x - w1.y * w2.y;
                const float wi = w1.x * w2.y + w1.y * w2.x;
                Cs[p * 65 + km] = make_float2(R * wr + I * wi, R * wi - I * wr);
            }
        }
    }
    if (tid < 64) {                               // C[p,32] = b32 * tw(p,32)
        const int p = tid;
        const int tt = p * 32;
        const float2 w1 = T64[tt >> 6], w2 = Tf[tt & 63];
        const float wr = w1.x * w2.x - w1.y * w2.y;
        const float wi = w1.x * w2.y + w1.y * w2.x;
        Cs[p * 65 + 32] = make_float2(b32 * wr, b32 * wi);
    }
    __syncthreads();

    // ---- Stage 2: Re(D[j,k]) for j = tid>>4 (0..31), k in {k0s + 16*ki} ----
    const int k0s = tid & 15;
    const int j   = tid >> 4;        // 0..31
    float dr[4] = {0.f, 0.f, 0.f, 0.f};
    int   u = 0;

    #pragma unroll 4
    for (int pp = 0; pp < 64; pp++) {
        const float2 w = T64[u];                  // <=2 addrs per warp
        u = (u + j) & 63;                         // u = pp*j mod 64
        #pragma unroll
        for (int ki = 0; ki < 4; ki++) {
            const float2 c = Cs[pp * 65 + k0s + 16 * ki];  // conflict-free
            dr[ki] = fmaf(w.x, c.x, fmaf(-w.y, c.y, dr[ki]));
        }
    }

    float* __restrict__ outr = out + (size_t)row * ROW_N;
    #pragma unroll
    for (int ki = 0; ki < 4; ki++) {
        const int k = k0s + 16 * ki;
        const int m = j * 64 + k;                 // 0..2047
        outr[m] = dr[ki];                         // coalesced
        if (m >= 1 && m <= 1984)                  // disjoint mirror set
            outr[ROW_N - m] = dr[ki];             // covers 2112..4095
    }

    // j = 32 row: D[2048+k].re = sum_p (-1)^p * Cs[p,k].x   (covers 2048..2111)
    if (tid < 64) {
        const int k = tid;
        float d32 = 0.f;
        #pragma unroll 8
        for (int p = 0; p < 64; p += 2)
            d32 += Cs[p * 65 + k].x - Cs[(p + 1) * 65 + k].x;
        outr[2048 + k] = d32;
    }
}

extern "C" void kernel_launch(void* const* d_in, const int* in_sizes, int n_in,
                              void* d_out, int out_size)
{
    const float* x = (const float*)d_in[0];
    const int nrows = in_sizes[0] / ROW_N;        // 4096 rows
    if (nrows <= 0) return;
    monarch_fft_kernel<<<nrows, THREADS>>>(x, (float*)d_out);
}

// round 5
// speedup vs baseline: 3.4178x; 1.6700x over previous
#include <cuda_runtime.h>
#include <cuda_bf16.h>

#define ROW_N 4096
#define THREADS 512

// Monarch FFT of real rows, output = Re(FFT(x)), P = Q = 64.
//   B[p,k]    = sum_q x[p+64q] e^{-2pi i qk/64}
//   C[p,k]    = B[p,k] e^{-2pi i pk/4096}
//   D[j,k]    = sum_p e^{-2pi i jp/64} C[p,k],  out[j*64+k] = Re(D)
// Symmetries: B[p,64-k] = conj(B[p,k]);  Re D[m] = Re D[4096-m].
//
// Twiddle trick: for k = kb + 8i,  T64[q(kb+8i)] = T64[q*kb] * tau,
// tau = e^{-2pi i m/8}, m = (q*i)&7.  Unrolling by 8 makes m compile-time:
// tau in {1,-1,+-i} is free; (+-1+-i)/sqrt2 costs 2 FMAs. One twiddle
// broadcast per warp per iteration instead of 2-4.

__device__ __forceinline__ float2 cs_get(const float2* Cs, int p, int k) {
    return Cs[p * 65 + k];
}

// Accumulate  (br,bi) += a * (wb * tau_M)   with a real.
template<int M>
__device__ __forceinline__ void s1_acc(float a, float ar, float2 wb,
                                       float s, float d, float& br, float& bi)
{
    if constexpr (M == 0)      { br = fmaf( a,  wb.x, br); bi = fmaf( a,  wb.y, bi); }
    else if constexpr (M == 1) { br = fmaf( ar, s,    br); bi = fmaf( ar, d,    bi); }
    else if constexpr (M == 2) { br = fmaf( a,  wb.y, br); bi = fmaf(-a,  wb.x, bi); }
    else if constexpr (M == 3) { br = fmaf( ar, d,    br); bi = fmaf(-ar, s,    bi); }
    else if constexpr (M == 4) { br = fmaf(-a,  wb.x, br); bi = fmaf(-a,  wb.y, bi); }
    else if constexpr (M == 5) { br = fmaf(-ar, s,    br); bi = fmaf(-ar, d,    bi); }
    else if constexpr (M == 6) { br = fmaf(-a,  wb.y, br); bi = fmaf( a,  wb.x, bi); }
    else                       { br = fmaf(-ar, d,    br); bi = fmaf( ar, s,    bi); }
}

// Re(u * tau_M):  us = r*(ux+uy), ud = r*(uy-ux)
template<int M>
__device__ __forceinline__ float pick_re(float ux, float uy, float us, float ud)
{
    if constexpr (M == 0)      return  ux;
    else if constexpr (M == 1) return  us;
    else if constexpr (M == 2) return  uy;
    else if constexpr (M == 3) return  ud;
    else if constexpr (M == 4) return -ux;
    else if constexpr (M == 5) return -us;
    else if constexpr (M == 6) return -uy;
    else                       return -ud;
}

template<int QQ>
__device__ __forceinline__ void s1_step(int q, int p0, int kb,
                                        const float* __restrict__ xs,
                                        const float2* __restrict__ T64,
                                        int& t, float (&br)[2][4], float (&bi)[2][4])
{
    const float2 wb = T64[t];                  // warp-uniform -> broadcast
    t = (t + kb) & 63;
    const float a0 = xs[p0      + (q << 6)];   // lanes consecutive -> 1 wf
    const float a1 = xs[p0 + 32 + (q << 6)];
    constexpr int M1 = (QQ * 1) & 7;
    constexpr int M2 = (QQ * 2) & 7;
    constexpr int M3 = (QQ * 3) & 7;
    constexpr bool needR = (M1 & 1) || (M3 & 1);
    const float RC = 0.70710678118654752440f;
    float s = 0.f, d = 0.f, ar0 = 0.f, ar1 = 0.f;
    if constexpr (needR) {
        s = wb.x + wb.y;  d = wb.y - wb.x;
        ar0 = a0 * RC;    ar1 = a1 * RC;
    }
    s1_acc<0 >(a0, ar0, wb, s, d, br[0][0], bi[0][0]);
    s1_acc<M1>(a0, ar0, wb, s, d, br[0][1], bi[0][1]);
    s1_acc<M2>(a0, ar0, wb, s, d, br[0][2], bi[0][2]);
    s1_acc<M3>(a0, ar0, wb, s, d, br[0][3], bi[0][3]);
    s1_acc<0 >(a1, ar1, wb, s, d, br[1][0], bi[1][0]);
    s1_acc<M1>(a1, ar1, wb, s, d, br[1][1], bi[1][1]);
    s1_acc<M2>(a1, ar1, wb, s, d, br[1][2], bi[1][2]);
    s1_acc<M3>(a1, ar1, wb, s, d, br[1][3], bi[1][3]);
}

template<int PP>
__device__ __forceinline__ void s2_step(int pp, int k, int jb,
                                        const float2* __restrict__ Cs,
                                        const float2* __restrict__ T64,
                                        int& t, float (&dr)[4])
{
    const float2 wb = T64[t];                  // warp-uniform -> broadcast
    t = (t + jb) & 63;
    const float2 c = cs_get(Cs, pp, k);        // lanes consecutive -> 2 wf
    const float ux = fmaf(wb.x, c.x, -(wb.y * c.y));
    const float uy = fmaf(wb.x, c.y,   wb.y * c.x);
    constexpr int M1 = (PP * 1) & 7;
    constexpr int M2 = (PP * 2) & 7;
    constexpr int M3 = (PP * 3) & 7;
    constexpr bool needR = (M1 & 1) || (M3 & 1);
    const float RC = 0.70710678118654752440f;
    float us = 0.f, ud = 0.f;
    if constexpr (needR) { us = RC * (ux + uy); ud = RC * (uy - ux); }
    dr[0] += ux;
    dr[1] += pick_re<M1>(ux, uy, us, ud);
    dr[2] += pick_re<M2>(ux, uy, us, ud);
    dr[3] += pick_re<M3>(ux, uy, us, ud);
}

__global__ void __launch_bounds__(THREADS, 2)
monarch_fft_kernel(const float* __restrict__ x, float* __restrict__ out)
{
    __shared__ float2 Cs[64 * 65];
    __shared__ float2 T64[64];
    __shared__ float2 Tf [64];
    float* xs = (float*)Cs;                    // overlays Cs; dead before C written

    const int row = blockIdx.x;
    const int tid = threadIdx.x;

    if (tid < 64) {
        float s, c;
        __sincosf(-6.28318530717958647692f * (float)tid * (1.0f / 64.0f), &s, &c);
        T64[tid] = make_float2(c, s);
        __sincosf(-6.28318530717958647692f * (float)tid * (1.0f / 4096.0f), &s, &c);
        Tf[tid] = make_float2(c, s);
    }

    const float* __restrict__ xr = x + (size_t)row * ROW_N;
    #pragma unroll
    for (int i = tid; i < ROW_N; i += THREADS) xs[i] = xr[i];
    __syncthreads();

    // ---- Stage 1: threads 0..255: p in {p0,p0+32}, k in {kb,kb+8,kb+16,kb+24}
    const int p0 = tid & 31;
    const int kb = (tid >> 5) & 7;
    float br[2][4], bi[2][4];
    #pragma unroll
    for (int a = 0; a < 2; a++)
        #pragma unroll
        for (int b = 0; b < 4; b++) { br[a][b] = 0.f; bi[a][b] = 0.f; }
    float b32 = 0.f;

    if (tid < 256) {
        int t = 0;
        #pragma unroll 1
        for (int q8 = 0; q8 < 64; q8 += 8) {
            s1_step<0>(q8 + 0, p0, kb, xs, T64, t, br, bi);
            s1_step<1>(q8 + 1, p0, kb, xs, T64, t, br, bi);
            s1_step<2>(q8 + 2, p0, kb, xs, T64, t, br, bi);
            s1_step<3>(q8 + 3, p0, kb, xs, T64, t, br, bi);
            s1_step<4>(q8 + 4, p0, kb, xs, T64, t, br, bi);
            s1_step<5>(q8 + 5, p0, kb, xs, T64, t, br, bi);
            s1_step<6>(q8 + 6, p0, kb, xs, T64, t, br, bi);
            s1_step<7>(q8 + 7, p0, kb, xs, T64, t, br, bi);
        }
    } else if (tid < 320) {
        // k = 32 column: B[p,32] = sum_q (-1)^q x[p+64q]   (otherwise-idle warps)
        const int p = tid - 256;
        #pragma unroll 8
        for (int q = 0; q < 64; q += 2)
            b32 += xs[p + (q << 6)] - xs[p + ((q + 1) << 6)];
    }
    __syncthreads();                           // xs dead -> Cs may overwrite

    // ---- Twiddle + write C (direct k and Hermitian mirror 64-k) ----
    if (tid < 256) {
        #pragma unroll
        for (int pi = 0; pi < 2; pi++) {
            const int p = p0 + 32 * pi;
            #pragma unroll
            for (int i = 0; i < 4; i++) {
                const int kk = kb + 8 * i;     // 0..31
                const float Rr = br[pi][i], Ii = bi[pi][i];
                {
                    const int tt = p * kk;     // < 4096
                    const float2 w1 = T64[tt >> 6], w2 = Tf[tt & 63];
                    const float wr = w1.x * w2.x - w1.y * w2.y;
                    const float wi = w1.x * w2.y + w1.y * w2.x;
                    Cs[p * 65 + kk] = make_float2(Rr * wr - Ii * wi,
                                                  Rr * wi + Ii * wr);
                }
                if (kk > 0) {
                    const int km = 64 - kk;
                    const int tt = p * km;
                    const float2 w1 = T64[tt >> 6], w2 = Tf[tt & 63];
                    const float wr = w1.x * w2.x - w1.y * w2.y;
                    const float wi = w1.x * w2.y + w1.y * w2.x;
                    Cs[p * 65 + km] = make_float2(Rr * wr + Ii * wi,
                                                  Rr * wi - Ii * wr);
                }
            }
        }
    } else if (tid < 320) {
        const int p = tid - 256;
        const int tt = p * 32;
        const float2 w1 = T64[tt >> 6], w2 = Tf[tt & 63];
        const float wr = w1.x * w2.x - w1.y * w2.y;
        const float wi = w1.x * w2.y + w1.y * w2.x;
        Cs[p * 65 + 32] = make_float2(b32 * wr, b32 * wi);
    }
    __syncthreads();

    // ---- Stage 2: all 512 threads: k = tid&63, j in {jb,jb+8,jb+16,jb+24} ----
    const int k  = tid & 63;
    const int jb = tid >> 6;                   // 0..7
    float dr[4] = {0.f, 0.f, 0.f, 0.f};
    {
        int t = 0;
        #pragma unroll 1
        for (int p8 = 0; p8 < 64; p8 += 8) {
            s2_step<0>(p8 + 0, k, jb, Cs, T64, t, dr);
            s2_step<1>(p8 + 1, k, jb, Cs, T64, t, dr);
            s2_step<2>(p8 + 2, k, jb, Cs, T64, t, dr);
            s2_step<3>(p8 + 3, k, jb, Cs, T64, t, dr);
            s2_step<4>(p8 + 4, k, jb, Cs, T64, t, dr);
            s2_step<5>(p8 + 5, k, jb, Cs, T64, t, dr);
            s2_step<6>(p8 + 6, k, jb, Cs, T64, t, dr);
            s2_step<7>(p8 + 7, k, jb, Cs, T64, t, dr);
        }
    }

    float* __restrict__ outr = out + (size_t)row * ROW_N;
    #pragma unroll
    for (int i = 0; i < 4; i++) {
        const int j = jb + 8 * i;              // 0..31
        const int m = j * 64 + k;              // 0..2047
        outr[m] = dr[i];
        if (m >= 1 && m <= 1984)               // mirror covers 2112..4095
            outr[ROW_N - m] = dr[i];
    }

    // j = 32 row: Re D[2048+k] = sum_p (-1)^p Cs[p,k].x  (covers 2048..2111)
    if (tid < 64) {
        float d32 = 0.f;
        #pragma unroll 8
        for (int p = 0; p < 64; p += 2)
            d32 += Cs[p * 65 + tid].x - Cs[(p + 1) * 65 + tid].x;
        outr[2048 + tid] = d32;
    }
}

extern "C" void kernel_launch(void* const* d_in, const int* in_sizes, int n_in,
                              void* d_out, int out_size)
{
    const float* x = (const float*)d_in[0];
    const int nrows = in_sizes[0] / ROW_N;     // 4096 rows
    if (nrows <= 0) return;
    monarch_fft_kernel<<<nrows, THREADS>>>(x, (float*)d_out);
}

// round 6
// speedup vs baseline: 5.1141x; 1.4963x over previous
#include <cuda_runtime.h>
#include <cuda_bf16.h>

#define ROW_N 4096
#define THREADS 512
#define RC 0.70710678118654752440f

// Monarch FFT, out = Re(FFT(x)) per 4096-pt row; P = Q = 64, and each 64-pt
// DFT is itself split 8x8 (Cooley-Tukey):
//   B[p, k1+8k2] = sum_q1 w64^{q1 k1} w8^{q1 k2} G[p,q1,k1]
//   G[p,q1,k1]   = sum_q2 x[p+64(q1+8q2)] w8^{q2 k1}
//   C[p,k]       = B[p,k] * w4096^{p k}
//   ReD[j1+8j2,k]= Re sum_p1 w8^{p1 j2} * ( w64^{p1 j1} *
//                       sum_p2 C[p1+8p2, k] w8^{p2 j1} )
// w8 rotations with compile-time exponent are free sign/swap/(+-r) selects.

__device__ __forceinline__ float2 cmulf(float2 a, float2 b) {
    return make_float2(fmaf(a.x, b.x, -(a.y * b.y)),
                       fmaf(a.x, b.y,   a.y * b.x));
}

// (bx,by) += h * e^{-2pi i M/8};  sh = r*(hx+hy), dh = r*(hy-hx)
template<int M>
__device__ __forceinline__ void rot_add(float hx, float hy, float sh, float dh,
                                        float& bx, float& by)
{
    if constexpr (M == 0)      { bx += hx; by += hy; }
    else if constexpr (M == 1) { bx += sh; by += dh; }
    else if constexpr (M == 2) { bx += hy; by -= hx; }
    else if constexpr (M == 3) { bx += dh; by -= sh; }
    else if constexpr (M == 4) { bx -= hx; by -= hy; }
    else if constexpr (M == 5) { bx -= sh; by -= dh; }
    else if constexpr (M == 6) { bx -= hy; by += hx; }
    else                       { bx -= dh; by += sh; }
}

// acc += Re( h * e^{-2pi i M/8} )
template<int M>
__device__ __forceinline__ void rot_add_re(float hx, float hy, float sh, float dh,
                                           float& acc)
{
    if constexpr (M == 0)      acc += hx;
    else if constexpr (M == 1) acc += sh;
    else if constexpr (M == 2) acc += hy;
    else if constexpr (M == 3) acc += dh;
    else if constexpr (M == 4) acc -= hx;
    else if constexpr (M == 5) acc -= sh;
    else if constexpr (M == 6) acc -= hy;
    else                       acc -= dh;
}

template<int K2>
__device__ __forceinline__ void gather8(const float (&Hx)[8], const float (&Hy)[8],
                                        const float (&sH)[8], const float (&dH)[8],
                                        float& bx, float& by)
{
    bx = Hx[0]; by = Hy[0];
    rot_add<(1*K2)&7>(Hx[1],Hy[1],sH[1],dH[1],bx,by);
    rot_add<(2*K2)&7>(Hx[2],Hy[2],sH[2],dH[2],bx,by);
    rot_add<(3*K2)&7>(Hx[3],Hy[3],sH[3],dH[3],bx,by);
    rot_add<(4*K2)&7>(Hx[4],Hy[4],sH[4],dH[4],bx,by);
    rot_add<(5*K2)&7>(Hx[5],Hy[5],sH[5],dH[5],bx,by);
    rot_add<(6*K2)&7>(Hx[6],Hy[6],sH[6],dH[6],bx,by);
    rot_add<(7*K2)&7>(Hx[7],Hy[7],sH[7],dH[7],bx,by);
}

template<int J2>
__device__ __forceinline__ float gather8_re(const float (&Hx)[8], const float (&Hy)[8],
                                            const float (&sH)[8], const float (&dH)[8])
{
    float acc = Hx[0];
    rot_add_re<(1*J2)&7>(Hx[1],Hy[1],sH[1],dH[1],acc);
    rot_add_re<(2*J2)&7>(Hx[2],Hy[2],sH[2],dH[2],acc);
    rot_add_re<(3*J2)&7>(Hx[3],Hy[3],sH[3],dH[3],acc);
    rot_add_re<(4*J2)&7>(Hx[4],Hy[4],sH[4],dH[4],acc);
    rot_add_re<(5*J2)&7>(Hx[5],Hy[5],sH[5],dH[5],acc);
    rot_add_re<(6*J2)&7>(Hx[6],Hy[6],sH[6],dH[6],acc);
    rot_add_re<(7*J2)&7>(Hx[7],Hy[7],sH[7],dH[7],acc);
    return acc;
}

__global__ void __launch_bounds__(THREADS, 2)
monarch_fft_kernel(const float* __restrict__ x, float* __restrict__ out)
{
    __shared__ float2 Cs[64 * 65];   // C[p][k], pitch 65
    __shared__ float2 T64[64];       // e^{-2pi i t/64}
    __shared__ float2 Tf [64];       // e^{-2pi i t/4096}
    float* xs = (float*)Cs;          // 4096-float overlay; dead before C writes

    const int tid = threadIdx.x;
    const int row = blockIdx.x;

    if (tid < 64) {
        float s, c;
        __sincosf(-6.28318530717958647692f * (float)tid * (1.0f / 64.0f), &s, &c);
        T64[tid] = make_float2(c, s);
        __sincosf(-6.28318530717958647692f * (float)tid * (1.0f / 4096.0f), &s, &c);
        Tf[tid] = make_float2(c, s);
    }

    {   // coalesced 16B row load
        const float4* __restrict__ xr4 = (const float4*)(x + (size_t)row * ROW_N);
        float4* xs4 = (float4*)xs;
        xs4[tid]       = xr4[tid];
        xs4[tid + 512] = xr4[tid + 512];
    }
    __syncthreads();

    // ================= Stage 1: thread = (p, k1) =================
    const int p  = tid & 63;
    const int k1 = tid >> 6;                       // warp-uniform

    float2 w8q[8];                                 // w8^{q2 k1}, broadcast loads
    #pragma unroll
    for (int m = 1; m < 8; m++) w8q[m] = T64[(8 * m * k1) & 63];

    float Hx[8], Hy[8], sH[8], dH[8];
    #pragma unroll
    for (int q1 = 0; q1 < 8; q1++) {
        float gx = xs[p + 64 * q1];                // q2 = 0 term
        float gy = 0.f;
        #pragma unroll
        for (int q2 = 1; q2 < 8; q2++) {
            const float a = xs[p + 64 * q1 + 512 * q2];  // conflict-free
            gx = fmaf(a, w8q[q2].x, gx);
            gy = fmaf(a, w8q[q2].y, gy);
        }
        const float2 W = T64[(q1 * k1) & 63];      // broadcast
        Hx[q1] = fmaf(gx, W.x, -(gy * W.y));
        Hy[q1] = fmaf(gx, W.y,   gy * W.x);
    }
    #pragma unroll
    for (int q1 = 0; q1 < 8; q1++) {
        sH[q1] = RC * (Hx[q1] + Hy[q1]);
        dH[q1] = RC * (Hy[q1] - Hx[q1]);
    }

    // incremental C-twiddle: cur = w4096^{p k1}, step = w4096^{8p}
    float2 cur, stp;
    {
        const int t0 = p * k1;                     // <= 441
        cur = cmulf(T64[t0 >> 6], Tf[t0 & 63]);
        const int ts = 8 * p;                      // <= 504
        stp = cmulf(T64[ts >> 6], Tf[ts & 63]);
    }
    __syncthreads();                               // all xs reads complete

    float2* __restrict__ Crow = Cs + p * 65;
    #define S1_STEP(K2) { \
        float bx, by; gather8<K2>(Hx, Hy, sH, dH, bx, by); \
        Crow[k1 + 8 * K2] = make_float2(fmaf(bx, cur.x, -(by * cur.y)), \
                                        fmaf(bx, cur.y,   by * cur.x)); \
        cur = cmulf(cur, stp); }
    S1_STEP(0) S1_STEP(1) S1_STEP(2) S1_STEP(3)
    S1_STEP(4) S1_STEP(5) S1_STEP(6) S1_STEP(7)
    #undef S1_STEP
    __syncthreads();

    // ================= Stage 2: thread = (k, j1) =================
    const int k  = tid & 63;
    const int j1 = tid >> 6;                       // warp-uniform

    float2 w8j[8];                                 // w8^{p2 j1}, broadcast
    #pragma unroll
    for (int m = 1; m < 8; m++) w8j[m] = T64[(8 * m * j1) & 63];

    float Ix[8], Iy[8], sI[8], dI[8];
    #pragma unroll
    for (int p1 = 0; p1 < 8; p1++) {
        float2 z0 = Cs[p1 * 65 + k];               // lanes consecutive, 64-bit
        float ex = z0.x, ey = z0.y;
        #pragma unroll
        for (int p2 = 1; p2 < 8; p2++) {
            const float2 z = Cs[(p1 + 8 * p2) * 65 + k];
            ex = fmaf(z.x, w8j[p2].x, fmaf(-z.y, w8j[p2].y, ex));
            ey = fmaf(z.x, w8j[p2].y, fmaf( z.y, w8j[p2].x, ey));
        }
        const float2 W = T64[(p1 * j1) & 63];      // broadcast
        Ix[p1] = fmaf(ex, W.x, -(ey * W.y));
        Iy[p1] = fmaf(ex, W.y,   ey * W.x);
        sI[p1] = RC * (Ix[p1] + Iy[p1]);
        dI[p1] = RC * (Iy[p1] - Ix[p1]);
    }

    float* __restrict__ outr = out + (size_t)row * ROW_N + k;
    #define S2_STEP(J2) \
        outr[(j1 + 8 * J2) * 64] = gather8_re<J2>(Ix, Iy, sI, dI);
    S2_STEP(0) S2_STEP(1) S2_STEP(2) S2_STEP(3)
    S2_STEP(4) S2_STEP(5) S2_STEP(6) S2_STEP(7)
    #undef S2_STEP
}

extern "C" void kernel_launch(void* const* d_in, const int* in_sizes, int n_in,
                              void* d_out, int out_size)
{
    const float* x = (const float*)d_in[0];
    const int nrows = in_sizes[0] / ROW_N;         // 4096 rows
    if (nrows <= 0) return;
    monarch_fft_kernel<<<nrows, THREADS>>>(x, (float*)d_out);
}